// round 7
// baseline (speedup 1.0000x reference)
#include <cuda_runtime.h>
#include <math.h>

#define S_LEN    4096
#define BATCH    8
#define DMODEL   256
#define NTHREADS 1024
#define NPAIRS   (S_LEN / 2)
#define ITEMS_TOTAL (BATCH * (S_LEN / 32))   // 1024 items of 32 queries
#define GRID     148
#define PAIRS_PER_WARP (NPAIRS / 32)         // 64

typedef unsigned long long ull;

__device__ __forceinline__ float ex2_fast(float x) {
    float r;
    asm("ex2.approx.ftz.f32 %0, %1;" : "=f"(r) : "f"(x));
    return r;
}
__device__ __forceinline__ ull pk2(float a, float b) {
    ull r; asm("mov.b64 %0, {%1, %2};" : "=l"(r) : "f"(a), "f"(b)); return r;
}
__device__ __forceinline__ void upk2(ull v, float& a, float& b) {
    asm("mov.b64 {%0, %1}, %2;" : "=f"(a), "=f"(b) : "l"(v));
}
__device__ __forceinline__ ull fma2(ull a, ull b, ull c) {
    ull r; asm("fma.rn.f32x2 %0, %1, %2, %3;" : "=l"(r) : "l"(a), "l"(b), "l"(c)); return r;
}
__device__ __forceinline__ ull add2(ull a, ull b) {
    ull r; asm("add.rn.f32x2 %0, %1, %2;" : "=l"(r) : "l"(a), "l"(b)); return r;
}

// fma-pipe exp2: clamp, magic round-to-int, deg-4 poly, exponent splice.
__device__ __forceinline__ float exp2_poly(float x) {
    const float MAGIC = 12582912.0f;   // 1.5 * 2^23
    float xc = fmaxf(x, -126.0f);
    float t  = xc + MAGIC;             // integer part in low mantissa bits
    float fi = t - MAGIC;
    float xf = xc - fi;                // in [-0.5, 0.5]
    float p = fmaf(0.0096181f, xf, 0.0557834f);
    p = fmaf(p, xf, 0.2401597f);
    p = fmaf(p, xf, 0.6931472f);
    p = fmaf(p, xf, 1.0000000f);
    int ib = __float_as_int(t) << 23;  // == i << 23 (magic mantissa bits shift out)
    return __int_as_float(__float_as_int(p) + ib);
}

__global__ __launch_bounds__(NTHREADS, 1)
void dwsa_kernel(const float* __restrict__ x,
                 const float* __restrict__ Wq,
                 const float* __restrict__ Wk,
                 const float* __restrict__ Wv,
                 float* __restrict__ out)
{
    __shared__ float4 kp[NPAIRS];       // {h0, h1, -sz0m, -sz1m} per key pair (32 KB)
    __shared__ float2 part[32][33];     // [query][key-chunk] partial (se, sw), padded
    __shared__ float  sWv[DMODEL];
    __shared__ float  sW[32];
    __shared__ float  redD[32];
    __shared__ float  redM[32];

    const int tid  = threadIdx.x;
    const int wid  = tid >> 5;          // key-chunk
    const int lane = tid & 31;          // query within item

    // ---- dot(Wq, Wk) once per CTA
    float p = (tid < DMODEL) ? Wq[tid] * Wk[tid] : 0.0f;
    #pragma unroll
    for (int o = 16; o; o >>= 1) p += __shfl_xor_sync(0xffffffffu, p, o);
    if (lane == 0) redD[wid] = p;
    if (tid < DMODEL) sWv[tid] = Wv[tid];
    __syncthreads();
    float dotqk = 0.0f;
    #pragma unroll
    for (int i = 0; i < 32; i++) dotqk += redD[i];

    const float LOG2E = 1.4426950408889634f;
    const float cs  = dotqk * (1.0f / 16.0f) * LOG2E;
    const float nB2 = -0.5f * LOG2E;
    const ull  nB22 = pk2(nB2, nB2);
    const ull  ABSM = 0x7fffffff7fffffffULL;

    const int start = (blockIdx.x * ITEMS_TOTAL) / GRID;
    const int end   = ((blockIdx.x + 1) * ITEMS_TOTAL) / GRID;

    int   cur_b = -1;
    float hmax  = 0.0f;

    for (int it = start; it < end; ++it) {
        const int b     = it >> 7;      // 128 items per batch
        const int chunk = it & 127;
        const float4* xb4 = (const float4*)(x + (size_t)b * S_LEN * 2); // {sz0,h0,sz1,h1}

        if (b != cur_b) {
            __syncthreads();            // everyone done with old keys/parts
            float hm = 0.0f;
            #pragma unroll
            for (int pi = tid; pi < NPAIRS; pi += NTHREADS) {
                float4 v = xb4[pi];
                float n0 = (v.y == 0.0f) ? -3.0e9f : -v.x;
                float n1 = (v.w == 0.0f) ? -3.0e9f : -v.z;
                kp[pi] = make_float4(v.y, v.w, n0, n1);
                hm = fmaxf(hm, fmaxf(fabsf(v.y), fabsf(v.w)));
            }
            #pragma unroll
            for (int o = 16; o; o >>= 1) hm = fmaxf(hm, __shfl_xor_sync(0xffffffffu, hm, o));
            if (lane == 0) redM[wid] = hm;
            __syncthreads();
            hm = redM[0];
            #pragma unroll
            for (int i = 1; i < 32; i++) hm = fmaxf(hm, redM[i]);
            hmax  = hm;
            cur_b = b;
        }

        // ---- this lane's query
        const int q = chunk * 32 + lane;
        const float2 qv = ((const float2*)xb4)[q];
        const float hq = qv.y;
        const float zq = qv.x;
        const float aq = cs * hq;
        const float nm = -fabsf(aq) * hmax;

        const ull aq2 = pk2(aq, aq);
        const ull nm2 = pk2(nm, nm);
        const ull zq2 = pk2(zq, zq);

        ull s2 = 0, w2 = 0, s2b = 0, w2b = 0;

        // ---- this warp's 64 key pairs, broadcast loads; 16-pair body: 13 MUFU + 3 poly
        const float4* wk = kp + wid * PAIRS_PER_WARP;
        #pragma unroll 1
        for (int kk = 0; kk < PAIRS_PER_WARP; kk += 16) {
            #pragma unroll
            for (int j = 0; j < 16; ++j) {
                float4 v = wk[kk + j];
                ull h2 = pk2(v.x, v.y);
                ull n2 = pk2(v.z, v.w);
                ull l2 = fma2(nB22, add2(zq2, n2) & ABSM, fma2(aq2, h2, nm2));
                float l0, l1; upk2(l2, l0, l1);
                float e0, e1;
                if (j < 13) { e0 = ex2_fast(l0);  e1 = ex2_fast(l1); }
                else        { e0 = exp2_poly(l0); e1 = exp2_poly(l1); }
                ull e2 = pk2(e0, e1);
                if (j & 1) { s2b = add2(s2b, e2); w2b = fma2(e2, h2, w2b); }
                else       { s2  = add2(s2,  e2); w2  = fma2(e2, h2, w2 ); }
            }
        }

        float s0, s1, sb0, sb1; upk2(s2, s0, s1); upk2(s2b, sb0, sb1);
        float u0, u1, ub0, ub1; upk2(w2, u0, u1); upk2(w2b, ub0, ub1);
        part[lane][wid] = make_float2((s0 + s1) + (sb0 + sb1),
                                      (u0 + u1) + (ub0 + ub1));
        __syncthreads();

        // ---- combine: warp 'wid' reduces query 'wid' over 32 key-chunk partials
        {
            float2 pr = part[wid][lane];
            float se = pr.x, sw = pr.y;
            #pragma unroll
            for (int o = 16; o; o >>= 1) {
                se += __shfl_xor_sync(0xffffffffu, se, o);
                sw += __shfl_xor_sync(0xffffffffu, sw, o);
            }
            if (lane == 0) sW[wid] = sw / se;
        }
        __syncthreads();

        // ---- epilogue: 32 rows x 64 float4
        float4* ob = (float4*)(out + ((size_t)b * S_LEN + (size_t)chunk * 32) * DMODEL);
        const float4* wv4 = (const float4*)sWv;
        #pragma unroll
        for (int i = tid; i < 32 * (DMODEL / 4); i += NTHREADS) {
            const int row = i >> 6;
            const float wv = sW[row];
            float4 vv = wv4[i & 63];
            vv.x *= wv; vv.y *= wv; vv.z *= wv; vv.w *= wv;
            ob[i] = vv;
        }
        __syncthreads();   // protect part[]/sW for next item
    }
}

extern "C" void kernel_launch(void* const* d_in, const int* in_sizes, int n_in,
                              void* d_out, int out_size)
{
    const float* x  = (const float*)d_in[0];
    const float* Wq = (const float*)d_in[1];
    const float* Wk = (const float*)d_in[2];
    const float* Wv = (const float*)d_in[3];
    float* out = (float*)d_out;

    dwsa_kernel<<<GRID, NTHREADS>>>(x, Wq, Wk, Wv, out);
}

// round 8
// speedup vs baseline: 1.0416x; 1.0416x over previous
#include <cuda_runtime.h>
#include <math.h>

#define S_LEN    4096
#define BATCH    8
#define DMODEL   256
#define NTHREADS 512
#define NWARPS   (NTHREADS / 32)            // 16
#define NPAIRS   (S_LEN / 2)                // 2048
#define PAIRS_PER_WARP (NPAIRS / NWARPS)    // 128
#define ITEMS_TOTAL (BATCH * (S_LEN / 32))  // 1024
#define GRID     444                        // 3 CTAs/SM * 148 SMs

typedef unsigned long long ull;

__device__ int g_ctr;

__device__ __forceinline__ float ex2_fast(float x) {
    float r;
    asm("ex2.approx.ftz.f32 %0, %1;" : "=f"(r) : "f"(x));
    return r;
}
__device__ __forceinline__ ull pk2(float a, float b) {
    ull r; asm("mov.b64 %0, {%1, %2};" : "=l"(r) : "f"(a), "f"(b)); return r;
}
__device__ __forceinline__ void upk2(ull v, float& a, float& b) {
    asm("mov.b64 {%0, %1}, %2;" : "=f"(a), "=f"(b) : "l"(v));
}
__device__ __forceinline__ ull fma2(ull a, ull b, ull c) {
    ull r; asm("fma.rn.f32x2 %0, %1, %2, %3;" : "=l"(r) : "l"(a), "l"(b), "l"(c)); return r;
}
__device__ __forceinline__ ull add2(ull a, ull b) {
    ull r; asm("add.rn.f32x2 %0, %1, %2;" : "=l"(r) : "l"(a), "l"(b)); return r;
}

// fma-pipe exp2: clamp, magic round, deg-4 poly, exponent splice (validated R7).
__device__ __forceinline__ float exp2_poly(float x) {
    const float MAGIC = 12582912.0f;   // 1.5 * 2^23
    float xc = fmaxf(x, -126.0f);
    float t  = xc + MAGIC;
    float fi = t - MAGIC;
    float xf = xc - fi;                // [-0.5, 0.5]
    float p = fmaf(0.0096181f, xf, 0.0557834f);
    p = fmaf(p, xf, 0.2401597f);
    p = fmaf(p, xf, 0.6931472f);
    p = fmaf(p, xf, 1.0000000f);
    int ib = __float_as_int(t) << 23;
    return __int_as_float(__float_as_int(p) + ib);
}

__global__ void dwsa_reset() { g_ctr = 0; }

__global__ __launch_bounds__(NTHREADS, 3)
void dwsa_kernel(const float* __restrict__ x,
                 const float* __restrict__ Wq,
                 const float* __restrict__ Wk,
                 const float* __restrict__ Wv,
                 float* __restrict__ out)
{
    __shared__ float4 kp[NPAIRS];            // {h0,h1,-sz0m,-sz1m}: 32 KB
    __shared__ float2 part[32][NWARPS + 1];  // [query][segment] (se, sw)
    __shared__ float  sWv[DMODEL];
    __shared__ float  redD[NWARPS];
    __shared__ float  redM[NWARPS];
    __shared__ int    sItem;

    const int tid  = threadIdx.x;
    const int wid  = tid >> 5;
    const int lane = tid & 31;

    // ---- dot(Wq, Wk) once
    float p = (tid < DMODEL) ? Wq[tid] * Wk[tid] : 0.0f;
    #pragma unroll
    for (int o = 16; o; o >>= 1) p += __shfl_xor_sync(0xffffffffu, p, o);
    if (lane == 0) redD[wid] = p;
    if (tid < DMODEL) sWv[tid] = Wv[tid];
    __syncthreads();
    float dotqk = 0.0f;
    #pragma unroll
    for (int i = 0; i < NWARPS; i++) dotqk += redD[i];

    const float LOG2E = 1.4426950408889634f;
    const float cs  = dotqk * (1.0f / 16.0f) * LOG2E;
    const float nB2 = -0.5f * LOG2E;
    const ull  nB22 = pk2(nB2, nB2);
    const ull  ABSM = 0x7fffffff7fffffffULL;

    int   cur_b = -1;
    float hmax  = 0.0f;

    for (;;) {
        // ---- steal one item (grain 1)
        if (tid == 0) sItem = atomicAdd(&g_ctr, 1);
        __syncthreads();
        const int it = sItem;
        if (it >= ITEMS_TOTAL) break;

        const int b     = it >> 7;      // 128 items per batch
        const int chunk = it & 127;
        const float4* xb4 = (const float4*)(x + (size_t)b * S_LEN * 2);

        if (b != cur_b) {
            // prior item's sync guarantees all warps are past kp reads
            float hm = 0.0f;
            #pragma unroll
            for (int pi = tid; pi < NPAIRS; pi += NTHREADS) {
                float4 v = xb4[pi];
                float n0 = (v.y == 0.0f) ? -3.0e9f : -v.x;
                float n1 = (v.w == 0.0f) ? -3.0e9f : -v.z;
                kp[pi] = make_float4(v.y, v.w, n0, n1);
                hm = fmaxf(hm, fmaxf(fabsf(v.y), fabsf(v.w)));
            }
            #pragma unroll
            for (int o = 16; o; o >>= 1) hm = fmaxf(hm, __shfl_xor_sync(0xffffffffu, hm, o));
            if (lane == 0) redM[wid] = hm;
            __syncthreads();
            hm = redM[0];
            #pragma unroll
            for (int i = 1; i < NWARPS; i++) hm = fmaxf(hm, redM[i]);
            hmax  = hm;
            cur_b = b;
        }

        // ---- this lane's query
        const int q = chunk * 32 + lane;
        const float2 qv = ((const float2*)xb4)[q];
        const float aq = cs * qv.y;
        const float nm = -fabsf(aq) * hmax;
        const ull aq2 = pk2(aq, aq);
        const ull nm2 = pk2(nm, nm);
        const ull zq2 = pk2(qv.x, qv.x);

        ull s2 = 0, w2 = 0, s2b = 0, w2b = 0;

        // ---- this warp's 128 pairs (broadcast); body of 8: 7 MUFU + 1 poly
        const float4* wk = kp + wid * PAIRS_PER_WARP;
        #pragma unroll 1
        for (int kk = 0; kk < PAIRS_PER_WARP; kk += 8) {
            #pragma unroll
            for (int j = 0; j < 8; ++j) {
                float4 v = wk[kk + j];
                ull h2 = pk2(v.x, v.y);
                ull n2 = pk2(v.z, v.w);
                ull l2 = fma2(nB22, add2(zq2, n2) & ABSM, fma2(aq2, h2, nm2));
                float l0, l1; upk2(l2, l0, l1);
                float e0, e1;
                if (j < 7) { e0 = ex2_fast(l0);  e1 = ex2_fast(l1); }
                else       { e0 = exp2_poly(l0); e1 = exp2_poly(l1); }
                ull e2 = pk2(e0, e1);
                if (j & 1) { s2b = add2(s2b, e2); w2b = fma2(e2, h2, w2b); }
                else       { s2  = add2(s2,  e2); w2  = fma2(e2, h2, w2 ); }
            }
        }

        float s0, s1, sb0, sb1; upk2(s2, s0, s1); upk2(s2b, sb0, sb1);
        float u0, u1, ub0, ub1; upk2(w2, u0, u1); upk2(w2b, ub0, ub1);
        part[lane][wid] = make_float2((s0 + s1) + (sb0 + sb1),
                                      (u0 + u1) + (ub0 + ub1));
        __syncthreads();   // the single per-item barrier

        // ---- combine + write: warp w handles queries 2w (lanes 0-15) and 2w+1 (16-31)
        {
            const int qh  = 2 * wid + (lane >> 4);
            const int seg = lane & 15;
            float2 pr = part[qh][seg];
            float se = pr.x, sw = pr.y;
            #pragma unroll
            for (int o = 8; o; o >>= 1) {
                se += __shfl_down_sync(0xffffffffu, se, o, 16);
                sw += __shfl_down_sync(0xffffffffu, sw, o, 16);
            }
            float r = sw / se;                                   // valid on lanes 0, 16
            const float wv0 = __shfl_sync(0xffffffffu, r, 0);
            const float wv1 = __shfl_sync(0xffffffffu, r, 16);

            const float4* wv4 = (const float4*)sWv;
            float4* r0 = (float4*)(out + ((size_t)b * S_LEN + chunk * 32 + 2 * wid) * DMODEL);
            float4* r1 = r0 + DMODEL / 4;
            #pragma unroll
            for (int c = lane; c < DMODEL / 4; c += 32) {
                float4 vv = wv4[c];
                float4 o0 = make_float4(vv.x * wv0, vv.y * wv0, vv.z * wv0, vv.w * wv0);
                float4 o1 = make_float4(vv.x * wv1, vv.y * wv1, vv.z * wv1, vv.w * wv1);
                r0[c] = o0;
                r1[c] = o1;
            }
        }
        // no trailing sync: next iteration's steal-sync protects part[]
    }
}

extern "C" void kernel_launch(void* const* d_in, const int* in_sizes, int n_in,
                              void* d_out, int out_size)
{
    const float* x  = (const float*)d_in[0];
    const float* Wq = (const float*)d_in[1];
    const float* Wk = (const float*)d_in[2];
    const float* Wv = (const float*)d_in[3];
    float* out = (float*)d_out;

    dwsa_reset<<<1, 1>>>();
    dwsa_kernel<<<GRID, NTHREADS>>>(x, Wq, Wk, Wv, out);
}